// round 2
// baseline (speedup 1.0000x reference)
#include <cuda_runtime.h>
#include <cuda_fp16.h>

#define NN      4096
#define HEADS   8
#define OUT_F   64
#define HT_N    512
#define NSPLIT  4
#define ITILE   128
#define JCHUNK  1024
#define JTILE   128
#define WPITCH  136   // halfs per sW row (272B, 16B aligned)
#define VPITCH  72    // halfs per sV row (144B, 16B aligned)

__device__ float    g_ht[NN * HT_N];
__device__ __half   g_V[(size_t)HEADS * NN * OUT_F];
__device__ float    g_nsS[HEADS * NN];
__device__ float    g_GS [HEADS * NN];
__device__ float    g_sD [HEADS * NN];
__device__ float    g_ED [HEADS * NN];
__device__ float    g_FD [HEADS * NN];
__device__ unsigned g_adjbits[NN * (NN / 32)];
__device__ float    g_acc[(size_t)NSPLIT * NN * HT_N];
__device__ float    g_Z  [NSPLIT * NN * HEADS];

// ---------------- K0: pack adjacency into bitmask ----------------
__global__ void k_pack_adj(const int* __restrict__ adj) {
    int idx = blockIdx.x * blockDim.x + threadIdx.x;   // 0 .. 4096*4096-1
    int v = adj[idx];
    unsigned m = __ballot_sync(0xffffffffu, v > 0);
    if ((threadIdx.x & 31) == 0) g_adjbits[idx >> 5] = m;
}

// ---------------- K1: ht = h @ W (fp32 SIMT), + fp16 V pack ----------------
__global__ void k_gemm_ht(const float* __restrict__ hmat, const float* __restrict__ W) {
    __shared__ float As[16][65];
    __shared__ float Bs[16][65];
    const int t = threadIdx.x;
    const int tx = t & 15, ty = t >> 4;
    const int rowBase = blockIdx.y * 64;
    const int colBase = blockIdx.x * 64;   // == head * 64

    float acc[4][4];
#pragma unroll
    for (int a = 0; a < 4; a++)
#pragma unroll
        for (int b = 0; b < 4; b++) acc[a][b] = 0.f;

    for (int k0 = 0; k0 < 256; k0 += 16) {
#pragma unroll
        for (int q = 0; q < 4; q++) {
            int kk = t & 15;
            int ii = (t >> 4) + q * 16;
            As[kk][ii] = hmat[(rowBase + ii) * 256 + k0 + kk];
            int nn = t & 63;
            int k2 = (t >> 6) + q * 4;
            Bs[k2][nn] = W[(k0 + k2) * HT_N + colBase + nn];
        }
        __syncthreads();
#pragma unroll
        for (int kk = 0; kk < 16; kk++) {
            float av[4], bv[4];
#pragma unroll
            for (int a = 0; a < 4; a++) av[a] = As[kk][a * 16 + ty];
#pragma unroll
            for (int b = 0; b < 4; b++) bv[b] = Bs[kk][b * 16 + tx];
#pragma unroll
            for (int a = 0; a < 4; a++)
#pragma unroll
                for (int b = 0; b < 4; b++) acc[a][b] += av[a] * bv[b];
        }
        __syncthreads();
    }
    const int head = colBase >> 6;
#pragma unroll
    for (int a = 0; a < 4; a++) {
        int r = rowBase + a * 16 + ty;
#pragma unroll
        for (int b = 0; b < 4; b++) {
            int c = b * 16 + tx;                 // 0..63 within head
            g_ht[r * HT_N + colBase + c] = acc[a][b];
            g_V[(size_t)head * NN * OUT_F + (size_t)r * OUT_F + c] = __float2half(acc[a][b]);
        }
    }
}

// ---------------- K2: scores + exponential factors ----------------
__global__ void k_scores(const float* __restrict__ avec) {
    const int n = blockIdx.x;
    const int wid = threadIdx.x >> 5;     // head
    const int lane = threadIdx.x & 31;
    const float* htp = g_ht + (size_t)n * HT_N + wid * OUT_F;
    float f0 = htp[lane], f1 = htp[lane + 32];
    float ssrc = f0 * avec[lane]      + f1 * avec[lane + 32];
    float sdst = f0 * avec[64 + lane] + f1 * avec[96 + lane];
#pragma unroll
    for (int o = 16; o > 0; o >>= 1) {
        ssrc += __shfl_xor_sync(0xffffffffu, ssrc, o);
        sdst += __shfl_xor_sync(0xffffffffu, sdst, o);
    }
    if (lane == 0) {
        int idx = wid * NN + n;
        g_nsS[idx] = -ssrc;
        g_GS[idx]  = expf(-0.8f * ssrc);
        g_sD[idx]  = sdst;
        g_ED[idx]  = expf(sdst);
        g_FD[idx]  = expf(0.2f * sdst);
    }
}

// ---------------- K3: fused masked-softmax attention (split-j) ----------------
// SMEM layout (bytes):
//   sW   [128*136] half : 0      .. 34816
//   sV   [128*72]  half : 34816  .. 53248
//   sSD  [128]     f32  : 53248
//   sED  [128]     f32  : 53760
//   sFD  [128]     f32  : 54272
//   sNS  [8*128]   f32  : 54784
//   sGS  [8*128]   f32  : 58880
//   sAdj [128*33]  u32  : 62976
//   zbuf [256]     f32  : 79872  .. 80896
#define ATTN_SMEM 80896

__global__ __launch_bounds__(256, 1) void k_attn() {
    extern __shared__ char smem_raw[];
    __half*   sW   = (__half*)(smem_raw);
    __half*   sV   = (__half*)(smem_raw + 34816);
    float*    sSD  = (float*)(smem_raw + 53248);
    float*    sED  = (float*)(smem_raw + 53760);
    float*    sFD  = (float*)(smem_raw + 54272);
    float*    sNS  = (float*)(smem_raw + 54784);
    float*    sGS  = (float*)(smem_raw + 58880);
    unsigned* sAdj = (unsigned*)(smem_raw + 62976);
    float*    zbuf = (float*)(smem_raw + 79872);

    const int t = threadIdx.x;
    const int itile = blockIdx.x;
    const int split = blockIdx.y;
    const int ig0 = itile * ITILE;
    const int jg0 = split * JCHUNK;

    // CTA-wide init: adj bits (rows i, this split's 1024-bit chunk) + per-i scalars
    for (int idx = t; idx < ITILE * 32; idx += 256) {
        int i = idx >> 5, w = idx & 31;
        sAdj[i * 33 + w] = g_adjbits[(ig0 + i) * (NN / 32) + (jg0 >> 5) + w];
    }
    for (int idx = t; idx < HEADS * ITILE; idx += 256) {
        int hh = idx >> 7, i = idx & 127;
        sNS[idx] = g_nsS[hh * NN + ig0 + i];
        sGS[idx] = g_GS [hh * NN + ig0 + i];
    }
    __syncthreads();

    const int wi   = t & 127;     // weight-gen: row in tile
    const int jh   = t >> 7;      // weight-gen: j half (0/1)
    const int wid  = t >> 5;      // mma: warp id
    const int lane = t & 31;
    const int l15  = lane & 15;
    const int lhi  = (lane >> 4) << 3;
    const unsigned sW_s = (unsigned)__cvta_generic_to_shared(sW);
    const unsigned sV_s = (unsigned)__cvta_generic_to_shared(sV);

    for (int h = 0; h < HEADS; ++h) {
        float acc[8][4];
#pragma unroll
        for (int x = 0; x < 8; x++)
#pragma unroll
            for (int y = 0; y < 4; y++) acc[x][y] = 0.f;
        float zsum = 0.f;
        const float nss = sNS[(h << 7) + wi];
        const float gs  = sGS[(h << 7) + wi];
        const __half* gVh = g_V + ((size_t)(h * NN + jg0)) * OUT_F;
        const float* gSDp = g_sD + h * NN + jg0;
        const float* gEDp = g_ED + h * NN + jg0;
        const float* gFDp = g_FD + h * NN + jg0;

        for (int jt = 0; jt < JCHUNK / JTILE; ++jt) {
            __syncthreads();   // previous mma done: safe to overwrite sSD/sED/sFD/sV/sW
            // per-tile j scalars
            if (t < 128) {
                sSD[t] = gSDp[jt * 128 + t];
                sED[t] = gEDp[jt * 128 + t];
            } else {
                sFD[t - 128] = gFDp[jt * 128 + (t - 128)];
            }
            // V tile: 128 rows x 64 halfs
            {
                const uint4* src = ((const uint4*)(gVh + (size_t)(jt * 128 + (t >> 1)) * OUT_F)) + (t & 1) * 4;
                uint4* dst = (uint4*)(sV + (t >> 1) * VPITCH + (t & 1) * 32);
                dst[0] = src[0]; dst[1] = src[1]; dst[2] = src[2]; dst[3] = src[3];
            }
            __syncthreads();   // scalars + V visible

            // ---- weight tile generation (no exp, no MUFU) ----
            {
                const unsigned aw0 = sAdj[wi * 33 + (jt << 2) + (jh << 1)];
                const unsigned aw1 = sAdj[wi * 33 + (jt << 2) + (jh << 1) + 1];
                __half* wrow = sW + wi * WPITCH + (jh << 6);
                const int jb = jh << 6;
#pragma unroll
                for (int q = 0; q < 64; q += 2) {
                    const unsigned bits = (q < 32) ? aw0 : aw1;
                    float w0 = (sSD[jb + q]     > nss) ? sED[jb + q]     : gs * sFD[jb + q];
                    float w1 = (sSD[jb + q + 1] > nss) ? sED[jb + q + 1] : gs * sFD[jb + q + 1];
                    if (!((bits >> (q & 31)) & 1u))       w0 = 0.f;
                    if (!((bits >> ((q + 1) & 31)) & 1u)) w1 = 0.f;
                    zsum += w0 + w1;
                    *(__half2*)(wrow + q) = __floats2half2_rn(w0, w1);
                }
            }
            __syncthreads();   // sW ready

            // ---- mma: C[128x64] += W[128x128] * V[128x64] ----
#pragma unroll
            for (int kt = 0; kt < 8; ++kt) {
                unsigned a0, a1, a2, a3;
                unsigned aAddr = sW_s + (((wid << 4) + l15) * WPITCH + (kt << 4) + lhi) * 2;
                asm volatile("ldmatrix.sync.aligned.m8n8.x4.shared.b16 {%0,%1,%2,%3}, [%4];\n"
                             : "=r"(a0), "=r"(a1), "=r"(a2), "=r"(a3) : "r"(aAddr));
#pragma unroll
                for (int ng = 0; ng < 4; ++ng) {
                    unsigned b0, b1, b2, b3;
                    unsigned bAddr = sV_s + (((kt << 4) + l15) * VPITCH + (ng << 4) + lhi) * 2;
                    asm volatile("ldmatrix.sync.aligned.m8n8.x4.trans.shared.b16 {%0,%1,%2,%3}, [%4];\n"
                                 : "=r"(b0), "=r"(b1), "=r"(b2), "=r"(b3) : "r"(bAddr));
                    asm volatile("mma.sync.aligned.m16n8k16.row.col.f32.f16.f16.f32 "
                                 "{%0,%1,%2,%3}, {%4,%5,%6,%7}, {%8,%9}, {%0,%1,%2,%3};\n"
                                 : "+f"(acc[2 * ng][0]), "+f"(acc[2 * ng][1]),
                                   "+f"(acc[2 * ng][2]), "+f"(acc[2 * ng][3])
                                 : "r"(a0), "r"(a1), "r"(a2), "r"(a3), "r"(b0), "r"(b1));
                    asm volatile("mma.sync.aligned.m16n8k16.row.col.f32.f16.f16.f32 "
                                 "{%0,%1,%2,%3}, {%4,%5,%6,%7}, {%8,%9}, {%0,%1,%2,%3};\n"
                                 : "+f"(acc[2 * ng + 1][0]), "+f"(acc[2 * ng + 1][1]),
                                   "+f"(acc[2 * ng + 1][2]), "+f"(acc[2 * ng + 1][3])
                                 : "r"(a0), "r"(a1), "r"(a2), "r"(a3), "r"(b2), "r"(b3));
                }
            }
        } // jt

        // Z partial reduce + write
        zbuf[(jh << 7) + wi] = zsum;
        __syncthreads();
        if (t < 128) {
            g_Z[split * NN * HEADS + (ig0 + t) * HEADS + h] = zbuf[t] + zbuf[128 + t];
        }
        // epilogue: accumulator -> global partial
        {
            const int r0 = ig0 + (wid << 4) + (lane >> 2);
            float* gaBase = g_acc + ((size_t)split << 21) + (size_t)r0 * HT_N + (h << 6) + ((lane & 3) << 1);
#pragma unroll
            for (int nt = 0; nt < 8; ++nt) {
                float* p = gaBase + (nt << 3);
                p[0]    = acc[nt][0];
                p[1]    = acc[nt][1];
                p[4096] = acc[nt][2];   // row +8  (8*512 floats)
                p[4097] = acc[nt][3];
            }
        }
    } // h
}

// ---------------- K4: combine splits, normalize, head-mean, LayerNorm ----------------
__global__ void k_finalize(const float* __restrict__ gamma, const float* __restrict__ beta,
                           float* __restrict__ out) {
    const int i = blockIdx.x;
    const int f = threadIdx.x;   // 0..63
    float m = 0.f;
#pragma unroll
    for (int h = 0; h < HEADS; h++) {
        float num = 0.f, z = 0.f;
#pragma unroll
        for (int s = 0; s < NSPLIT; s++) {
            num += g_acc[((size_t)s << 21) + (size_t)i * HT_N + h * OUT_F + f];
            z   += g_Z[s * NN * HEADS + i * HEADS + h];
        }
        m += num / z;
    }
    m *= (1.f / HEADS);

    __shared__ float red[64];
    red[f] = m;
    __syncthreads();
#pragma unroll
    for (int o = 32; o > 0; o >>= 1) {
        if (f < o) red[f] += red[f + o];
        __syncthreads();
    }
    float mu = red[0] * (1.f / 64.f);
    __syncthreads();
    float d = m - mu;
    red[f] = d * d;
    __syncthreads();
#pragma unroll
    for (int o = 32; o > 0; o >>= 1) {
        if (f < o) red[f] += red[f + o];
        __syncthreads();
    }
    float var = red[0] * (1.f / 64.f);
    out[i * OUT_F + f] = d * rsqrtf(var + 1e-5f) * gamma[f] + beta[f];
}

// ---------------- launch ----------------
extern "C" void kernel_launch(void* const* d_in, const int* in_sizes, int n_in,
                              void* d_out, int out_size) {
    const float* hmat  = (const float*)d_in[0];
    const int*   adj   = (const int*)  d_in[1];
    const float* W     = (const float*)d_in[2];
    const float* avec  = (const float*)d_in[3];
    const float* gamma = (const float*)d_in[4];
    const float* beta  = (const float*)d_in[5];
    float* out = (float*)d_out;

    k_pack_adj<<<(NN * NN) / 256, 256>>>(adj);
    k_gemm_ht<<<dim3(HT_N / 64, NN / 64), 256>>>(hmat, W);
    k_scores<<<NN, 256>>>(avec);
    cudaFuncSetAttribute(k_attn, cudaFuncAttributeMaxDynamicSharedMemorySize, ATTN_SMEM);
    k_attn<<<dim3(NN / ITILE, NSPLIT), 256, ATTN_SMEM>>>();
    k_finalize<<<NN, 64>>>(gamma, beta, out);
}

// round 3
// speedup vs baseline: 1.5654x; 1.5654x over previous
#include <cuda_runtime.h>
#include <cuda_fp16.h>

#define NN      4096
#define HEADS   8
#define OUT_F   64
#define HT_N    512
#define NSPLIT  4
#define HGRP    2
#define HPERG   4
#define ITILE   128
#define JCHUNK  1024
#define VPITCH  72    // halfs per sV row (144B)

__device__ float    g_ht[NN * HT_N];
__device__ __half   g_V[(size_t)HEADS * NN * OUT_F];
__device__ float    g_nsS[HEADS * NN];
__device__ float    g_GS [HEADS * NN];
__device__ float    g_sD [HEADS * NN];
__device__ float    g_ED [HEADS * NN];
__device__ float    g_FD [HEADS * NN];
__device__ unsigned g_adjbits[NN * (NN / 32)];
__device__ float    g_acc[(size_t)NSPLIT * NN * HT_N];
__device__ float    g_Z  [NSPLIT * NN * HEADS];

// ---------------- K0: pack adjacency into bitmask ----------------
__global__ void k_pack_adj(const int* __restrict__ adj) {
    int idx = blockIdx.x * blockDim.x + threadIdx.x;
    int v = adj[idx];
    unsigned m = __ballot_sync(0xffffffffu, v > 0);
    if ((threadIdx.x & 31) == 0) g_adjbits[idx >> 5] = m;
}

// ---------------- K1: ht = h @ W (fp32 SIMT), + fp16 V pack ----------------
__global__ void k_gemm_ht(const float* __restrict__ hmat, const float* __restrict__ W) {
    __shared__ float As[16][65];
    __shared__ float Bs[16][65];
    const int t = threadIdx.x;
    const int tx = t & 15, ty = t >> 4;
    const int rowBase = blockIdx.y * 64;
    const int colBase = blockIdx.x * 64;

    float acc[4][4];
#pragma unroll
    for (int a = 0; a < 4; a++)
#pragma unroll
        for (int b = 0; b < 4; b++) acc[a][b] = 0.f;

    for (int k0 = 0; k0 < 256; k0 += 16) {
#pragma unroll
        for (int q = 0; q < 4; q++) {
            int kk = t & 15;
            int ii = (t >> 4) + q * 16;
            As[kk][ii] = hmat[(rowBase + ii) * 256 + k0 + kk];
            int nn = t & 63;
            int k2 = (t >> 6) + q * 4;
            Bs[k2][nn] = W[(k0 + k2) * HT_N + colBase + nn];
        }
        __syncthreads();
#pragma unroll
        for (int kk = 0; kk < 16; kk++) {
            float av[4], bv[4];
#pragma unroll
            for (int a = 0; a < 4; a++) av[a] = As[kk][a * 16 + ty];
#pragma unroll
            for (int b = 0; b < 4; b++) bv[b] = Bs[kk][b * 16 + tx];
#pragma unroll
            for (int a = 0; a < 4; a++)
#pragma unroll
                for (int b = 0; b < 4; b++) acc[a][b] += av[a] * bv[b];
        }
        __syncthreads();
    }
    const int head = colBase >> 6;
#pragma unroll
    for (int a = 0; a < 4; a++) {
        int r = rowBase + a * 16 + ty;
#pragma unroll
        for (int b = 0; b < 4; b++) {
            int c = b * 16 + tx;
            g_ht[r * HT_N + colBase + c] = acc[a][b];
            g_V[(size_t)head * NN * OUT_F + (size_t)r * OUT_F + c] = __float2half(acc[a][b]);
        }
    }
}

// ---------------- K2: scores + exponential factors ----------------
__global__ void k_scores(const float* __restrict__ avec) {
    const int n = blockIdx.x;
    const int wid = threadIdx.x >> 5;
    const int lane = threadIdx.x & 31;
    const float* htp = g_ht + (size_t)n * HT_N + wid * OUT_F;
    float f0 = htp[lane], f1 = htp[lane + 32];
    float ssrc = f0 * avec[lane]      + f1 * avec[lane + 32];
    float sdst = f0 * avec[64 + lane] + f1 * avec[96 + lane];
#pragma unroll
    for (int o = 16; o > 0; o >>= 1) {
        ssrc += __shfl_xor_sync(0xffffffffu, ssrc, o);
        sdst += __shfl_xor_sync(0xffffffffu, sdst, o);
    }
    if (lane == 0) {
        int idx = wid * NN + n;
        g_nsS[idx] = -ssrc;
        g_GS[idx]  = expf(-0.8f * ssrc);
        g_sD[idx]  = sdst;
        g_ED[idx]  = expf(sdst);
        g_FD[idx]  = expf(0.2f * sdst);
    }
}

// ---------------- K3: fused attention, register-resident W fragments ----------------
// SMEM: sV[2][128*72]h : 0..36864 | sSD[2][128] 36864 | sED[2][128] 37888 |
//       sFD[2][128] 38912 | sAdj[128*33]u32 39936..56832
#define SV_BYTES  18432
#define SM_SD     36864
#define SM_ADJ    39936
#define ATTN_SMEM 56832

__device__ __forceinline__ void cp16(unsigned dst, const void* src) {
    asm volatile("cp.async.cg.shared.global [%0], [%1], 16;"
                 :: "r"(dst), "l"(__cvta_generic_to_global(src)));
}
__device__ __forceinline__ unsigned packh2(float x, float y) {
    __half2 h = __floats2half2_rn(x, y);
    return *reinterpret_cast<unsigned*>(&h);
}

__global__ __launch_bounds__(256, 2) void k_attn() {
    extern __shared__ char smem[];
    const unsigned sbase = (unsigned)__cvta_generic_to_shared(smem);
    float*    sSD  = (float*)(smem + SM_SD);          // [2][128]+[2][128]+[2][128]
    unsigned* sAdj = (unsigned*)(smem + SM_ADJ);

    const int t = threadIdx.x;
    const int ig0 = blockIdx.x * ITILE;
    const int split = blockIdx.y;
    const int jg0 = split * JCHUNK;
    const int hbase = blockIdx.z * HPERG;

    // adjacency bits for this (itile, split)
    for (int idx = t; idx < ITILE * 32; idx += 256) {
        int i = idx >> 5, w = idx & 31;
        sAdj[i * 33 + w] = g_adjbits[(ig0 + i) * (NN / 32) + (jg0 >> 5) + w];
    }

    const int lane = t & 31;
    const int wid  = t >> 5;
    const int l15  = lane & 15;
    const int lhi  = (lane >> 4) << 3;
    const int r0   = (wid << 4) + (lane >> 2);   // tile-local row
    const int r1   = r0 + 8;
    const int qc   = (lane & 3) << 1;            // col base within k16
    const int vrow = t >> 1;                     // V-load row
    const int vhf  = t & 1;

    // initial prefetch (m=0)
    {
        const __half* vsrc = g_V + ((size_t)(hbase * NN) + jg0) * OUT_F;
        const char* src = (const char*)(vsrc + (size_t)vrow * OUT_F) + vhf * 64;
        unsigned d = sbase + vrow * 144 + vhf * 64;
        cp16(d, src); cp16(d + 16, src + 16); cp16(d + 32, src + 32); cp16(d + 48, src + 48);
        if (t < 96) {
            int a = t >> 5, c = t & 31;
            const float* sc = (a == 0 ? g_sD : a == 1 ? g_ED : g_FD) + hbase * NN + jg0;
            cp16(sbase + SM_SD + a * 1024 + c * 16, (const char*)sc + c * 16);
        }
        asm volatile("cp.async.commit_group;");
    }

    for (int hh = 0; hh < HPERG; ++hh) {
        const int h = hbase + hh;
        const float nss0 = g_nsS[h * NN + ig0 + r0];
        const float nss1 = g_nsS[h * NN + ig0 + r1];
        const float gs0  = g_GS [h * NN + ig0 + r0];
        const float gs1  = g_GS [h * NN + ig0 + r1];

        float acc[8][4];
#pragma unroll
        for (int x = 0; x < 8; x++)
#pragma unroll
            for (int y = 0; y < 4; y++) acc[x][y] = 0.f;
        float zs0 = 0.f, zs1 = 0.f;

        for (int jt = 0; jt < 8; ++jt) {
            const int m = hh * 8 + jt;
            const int buf = m & 1;
            asm volatile("cp.async.wait_group 0;");
            __syncthreads();   // buffer m ready; all threads done with m-1's buffer

            // prefetch m+1 into other buffer
            if (m + 1 < HPERG * 8) {
                const int m2 = m + 1;
                const int h2 = hbase + (m2 >> 3), jt2 = m2 & 7, buf2 = m2 & 1;
                const __half* vsrc = g_V + ((size_t)(h2 * NN) + jg0 + jt2 * 128) * OUT_F;
                const char* src = (const char*)(vsrc + (size_t)vrow * OUT_F) + vhf * 64;
                unsigned d = sbase + buf2 * SV_BYTES + vrow * 144 + vhf * 64;
                cp16(d, src); cp16(d + 16, src + 16); cp16(d + 32, src + 32); cp16(d + 48, src + 48);
                if (t < 96) {
                    int a = t >> 5, c = t & 31;
                    const float* sc = (a == 0 ? g_sD : a == 1 ? g_ED : g_FD) + h2 * NN + jg0 + jt2 * 128;
                    cp16(sbase + SM_SD + a * 1024 + buf2 * 512 + c * 16, (const char*)sc + c * 16);
                }
            }
            asm volatile("cp.async.commit_group;");

            const float* pSD = sSD + buf * 128;
            const float* pED = sSD + 256 + buf * 128;
            const float* pFD = sSD + 512 + buf * 128;

            unsigned aw0[4], aw1[4];
#pragma unroll
            for (int w = 0; w < 4; w++) {
                aw0[w] = sAdj[r0 * 33 + (jt << 2) + w];
                aw1[w] = sAdj[r1 * 33 + (jt << 2) + w];
            }
            const unsigned vbase = sbase + buf * SV_BYTES;

#pragma unroll
            for (int kt = 0; kt < 8; ++kt) {
                const int c0 = (kt << 4) + qc;
                const float2 sdL = *(const float2*)(pSD + c0);
                const float2 sdH = *(const float2*)(pSD + c0 + 8);
                const float2 edL = *(const float2*)(pED + c0);
                const float2 edH = *(const float2*)(pED + c0 + 8);
                const float2 fdL = *(const float2*)(pFD + c0);
                const float2 fdH = *(const float2*)(pFD + c0 + 8);
                const int sh = ((kt & 1) << 4) + qc;
                const unsigned w0 = aw0[kt >> 1] >> sh;
                const unsigned w1 = aw1[kt >> 1] >> sh;

                float e00 = (w0 & 1u)         ? ((sdL.x > nss0) ? edL.x : gs0 * fdL.x) : 0.f;
                float e01 = (w0 & 2u)         ? ((sdL.y > nss0) ? edL.y : gs0 * fdL.y) : 0.f;
                float e02 = ((w0 >> 8) & 1u)  ? ((sdH.x > nss0) ? edH.x : gs0 * fdH.x) : 0.f;
                float e03 = ((w0 >> 9) & 1u)  ? ((sdH.y > nss0) ? edH.y : gs0 * fdH.y) : 0.f;
                float e10 = (w1 & 1u)         ? ((sdL.x > nss1) ? edL.x : gs1 * fdL.x) : 0.f;
                float e11 = (w1 & 2u)         ? ((sdL.y > nss1) ? edL.y : gs1 * fdL.y) : 0.f;
                float e12 = ((w1 >> 8) & 1u)  ? ((sdH.x > nss1) ? edH.x : gs1 * fdH.x) : 0.f;
                float e13 = ((w1 >> 9) & 1u)  ? ((sdH.y > nss1) ? edH.y : gs1 * fdH.y) : 0.f;

                zs0 += (e00 + e01) + (e02 + e03);
                zs1 += (e10 + e11) + (e12 + e13);

                const unsigned a0 = packh2(e00, e01);
                const unsigned a1 = packh2(e10, e11);
                const unsigned a2 = packh2(e02, e03);
                const unsigned a3 = packh2(e12, e13);

#pragma unroll
                for (int ng = 0; ng < 4; ++ng) {
                    unsigned b0, b1, b2, b3;
                    unsigned bAddr = vbase + (((kt << 4) + l15) * VPITCH + (ng << 4) + lhi) * 2;
                    asm volatile("ldmatrix.sync.aligned.m8n8.x4.trans.shared.b16 {%0,%1,%2,%3}, [%4];\n"
                                 : "=r"(b0), "=r"(b1), "=r"(b2), "=r"(b3) : "r"(bAddr));
                    asm volatile("mma.sync.aligned.m16n8k16.row.col.f32.f16.f16.f32 "
                                 "{%0,%1,%2,%3}, {%4,%5,%6,%7}, {%8,%9}, {%0,%1,%2,%3};\n"
                                 : "+f"(acc[2 * ng][0]), "+f"(acc[2 * ng][1]),
                                   "+f"(acc[2 * ng][2]), "+f"(acc[2 * ng][3])
                                 : "r"(a0), "r"(a1), "r"(a2), "r"(a3), "r"(b0), "r"(b1));
                    asm volatile("mma.sync.aligned.m16n8k16.row.col.f32.f16.f16.f32 "
                                 "{%0,%1,%2,%3}, {%4,%5,%6,%7}, {%8,%9}, {%0,%1,%2,%3};\n"
                                 : "+f"(acc[2 * ng + 1][0]), "+f"(acc[2 * ng + 1][1]),
                                   "+f"(acc[2 * ng + 1][2]), "+f"(acc[2 * ng + 1][3])
                                 : "r"(a0), "r"(a1), "r"(a2), "r"(a3), "r"(b2), "r"(b3));
                }
            }
        } // jt

        // Z: reduce across the 4 col-owning lanes, write per row
        zs0 += __shfl_xor_sync(0xffffffffu, zs0, 1);
        zs0 += __shfl_xor_sync(0xffffffffu, zs0, 2);
        zs1 += __shfl_xor_sync(0xffffffffu, zs1, 1);
        zs1 += __shfl_xor_sync(0xffffffffu, zs1, 2);
        if ((lane & 3) == 0) {
            g_Z[split * NN * HEADS + (ig0 + r0) * HEADS + h] = zs0;
            g_Z[split * NN * HEADS + (ig0 + r1) * HEADS + h] = zs1;
        }

        // epilogue: accumulator -> global partials
        {
            float* gaBase = g_acc + ((size_t)split << 21) + (size_t)(ig0 + r0) * HT_N + (h << 6) + qc;
#pragma unroll
            for (int nt = 0; nt < 8; ++nt) {
                float* p = gaBase + (nt << 3);
                p[0]    = acc[nt][0];
                p[1]    = acc[nt][1];
                p[4096] = acc[nt][2];
                p[4097] = acc[nt][3];
            }
        }
    } // hh
}

// ---------------- K4: combine splits, normalize, head-mean, LayerNorm ----------------
__global__ void k_finalize(const float* __restrict__ gamma, const float* __restrict__ beta,
                           float* __restrict__ out) {
    const int i = blockIdx.x;
    const int f = threadIdx.x;
    float m = 0.f;
#pragma unroll
    for (int h = 0; h < HEADS; h++) {
        float num = 0.f, z = 0.f;
#pragma unroll
        for (int s = 0; s < NSPLIT; s++) {
            num += g_acc[((size_t)s << 21) + (size_t)i * HT_N + h * OUT_F + f];
            z   += g_Z[s * NN * HEADS + i * HEADS + h];
        }
        m += num / z;
    }
    m *= (1.f / HEADS);

    __shared__ float red[64];
    red[f] = m;
    __syncthreads();
#pragma unroll
    for (int o = 32; o > 0; o >>= 1) {
        if (f < o) red[f] += red[f + o];
        __syncthreads();
    }
    float mu = red[0] * (1.f / 64.f);
    __syncthreads();
    float d = m - mu;
    red[f] = d * d;
    __syncthreads();
#pragma unroll
    for (int o = 32; o > 0; o >>= 1) {
        if (f < o) red[f] += red[f + o];
        __syncthreads();
    }
    float var = red[0] * (1.f / 64.f);
    out[i * OUT_F + f] = d * rsqrtf(var + 1e-5f) * gamma[f] + beta[f];
}

// ---------------- launch ----------------
extern "C" void kernel_launch(void* const* d_in, const int* in_sizes, int n_in,
                              void* d_out, int out_size) {
    const float* hmat  = (const float*)d_in[0];
    const int*   adj   = (const int*)  d_in[1];
    const float* W     = (const float*)d_in[2];
    const float* avec  = (const float*)d_in[3];
    const float* gamma = (const float*)d_in[4];
    const float* beta  = (const float*)d_in[5];
    float* out = (float*)d_out;

    k_pack_adj<<<(NN * NN) / 256, 256>>>(adj);
    k_gemm_ht<<<dim3(HT_N / 64, NN / 64), 256>>>(hmat, W);
    k_scores<<<NN, 256>>>(avec);
    cudaFuncSetAttribute(k_attn, cudaFuncAttributeMaxDynamicSharedMemorySize, ATTN_SMEM);
    k_attn<<<dim3(NN / ITILE, NSPLIT, HGRP), 256, ATTN_SMEM>>>();
    k_finalize<<<NN, 64>>>(gamma, beta, out);
}

// round 4
// speedup vs baseline: 1.9390x; 1.2387x over previous
#include <cuda_runtime.h>
#include <cuda_fp16.h>

#define NN      4096
#define HEADS   8
#define OUT_F   64
#define NSPLIT  4
#define HGRP    2
#define HPERG   4
#define ITILE   128
#define JCHUNK  1024
#define VPITCH  72     // halfs per sV row (144B)

__device__ __half   g_hh[NN * 256];
__device__ __half   g_Wh[256 * 512];
__device__ __half   g_V[(size_t)HEADS * NN * OUT_F];
__device__ __half   g_nssh[HEADS * NN];
__device__ __half   g_gsh [HEADS * NN];
__device__ __half   g_sDh [HEADS * NN];
__device__ __half   g_EDh [HEADS * NN];
__device__ __half   g_FDh [HEADS * NN];
__device__ unsigned g_adjbits[NN * (NN / 32)];
__device__ float    g_acc[(size_t)NSPLIT * NN * 512];
__device__ float    g_Z  [NSPLIT * NN * HEADS];

__device__ __forceinline__ void cp16(unsigned dst, const void* src) {
    asm volatile("cp.async.cg.shared.global [%0], [%1], 16;"
                 :: "r"(dst), "l"(__cvta_generic_to_global(src)));
}
__device__ __forceinline__ __half2 u2h2(unsigned x) { return *reinterpret_cast<__half2*>(&x); }
__device__ __forceinline__ unsigned h22u(__half2 x) { return *reinterpret_cast<unsigned*>(&x); }
// 2 adjacency bits -> half2 keep-mask
__device__ __forceinline__ unsigned bmask(unsigned b) {
    return ((b & 1u) * 0xFFFFu) | ((b & 2u) * 0x7FFF8000u);
}
// w = adj ? (sd > nss ? ed : gs*fd) : 0   (all half2)
__device__ __forceinline__ unsigned wval(unsigned sd, unsigned ed, __half2 neg,
                                         __half2 nss2, unsigned am) {
    unsigned cm = __hgt2_mask(u2h2(sd), nss2);
    return ((ed & cm) | (h22u(neg) & ~cm)) & am;
}
__device__ __forceinline__ void mma16816(float* c, unsigned a0, unsigned a1,
                                         unsigned a2, unsigned a3,
                                         unsigned b0, unsigned b1) {
    asm volatile("mma.sync.aligned.m16n8k16.row.col.f32.f16.f16.f32 "
                 "{%0,%1,%2,%3}, {%4,%5,%6,%7}, {%8,%9}, {%0,%1,%2,%3};\n"
                 : "+f"(c[0]), "+f"(c[1]), "+f"(c[2]), "+f"(c[3])
                 : "r"(a0), "r"(a1), "r"(a2), "r"(a3), "r"(b0), "r"(b1));
}

// ---------------- K0: pack adjacency into bitmask ----------------
__global__ void k_pack_adj(const int* __restrict__ adj) {
    int idx = blockIdx.x * blockDim.x + threadIdx.x;
    int v = adj[idx];
    unsigned m = __ballot_sync(0xffffffffu, v > 0);
    if ((threadIdx.x & 31) == 0) g_adjbits[idx >> 5] = m;
}

// ---------------- K0b: convert h, W to half ----------------
__global__ void k_cvt(const float* __restrict__ hmat, const float* __restrict__ W) {
    int i = blockIdx.x * 256 + threadIdx.x;
    if (i < 262144) {
        float4 v = ((const float4*)hmat)[i];
        ((__half2*)g_hh)[2 * i]     = __floats2half2_rn(v.x, v.y);
        ((__half2*)g_hh)[2 * i + 1] = __floats2half2_rn(v.z, v.w);
    } else {
        int j = i - 262144;
        float4 v = ((const float4*)W)[j];
        ((__half2*)g_Wh)[2 * j]     = __floats2half2_rn(v.x, v.y);
        ((__half2*)g_Wh)[2 * j + 1] = __floats2half2_rn(v.z, v.w);
    }
}

// ---------------- K1: ht = h @ W via fp16 tensor cores -> g_V (half) ----------------
__global__ __launch_bounds__(256) void k_gemm_ht() {
    __shared__ __align__(16) __half sA[128 * 72];
    __shared__ __align__(16) __half sB[64 * 72];
    const int t = threadIdx.x, lane = t & 31, wid = t >> 5;
    const int head = blockIdx.x, rowBase = blockIdx.y * 128;
    const int l15 = lane & 15, lhi = (lane >> 4) << 3, qc = (lane & 3) << 1;
    const unsigned sAb = (unsigned)__cvta_generic_to_shared(sA);
    const unsigned sBb = (unsigned)__cvta_generic_to_shared(sB);

    float acc[8][4];
#pragma unroll
    for (int x = 0; x < 8; x++)
#pragma unroll
        for (int y = 0; y < 4; y++) acc[x][y] = 0.f;

    for (int k0 = 0; k0 < 256; k0 += 64) {
        __syncthreads();
        {
            const char* src = (const char*)(g_hh + (size_t)(rowBase + (t >> 1)) * 256 + k0 + (t & 1) * 32);
            unsigned d = sAb + ((t >> 1) * 72 + (t & 1) * 32) * 2;
            cp16(d, src); cp16(d + 16, src + 16); cp16(d + 32, src + 32); cp16(d + 48, src + 48);
        }
        if (t < 128) {
            const char* src = (const char*)(g_Wh + (size_t)(k0 + (t >> 1)) * 512 + head * 64 + (t & 1) * 32);
            unsigned d = sBb + ((t >> 1) * 72 + (t & 1) * 32) * 2;
            cp16(d, src); cp16(d + 16, src + 16); cp16(d + 32, src + 32); cp16(d + 48, src + 48);
        }
        asm volatile("cp.async.commit_group;");
        asm volatile("cp.async.wait_group 0;");
        __syncthreads();
#pragma unroll
        for (int kt = 0; kt < 4; ++kt) {
            unsigned a0, a1, a2, a3;
            unsigned aAddr = sAb + (((wid << 4) + l15) * 72 + (kt << 4) + lhi) * 2;
            asm volatile("ldmatrix.sync.aligned.m8n8.x4.shared.b16 {%0,%1,%2,%3}, [%4];\n"
                         : "=r"(a0), "=r"(a1), "=r"(a2), "=r"(a3) : "r"(aAddr));
#pragma unroll
            for (int ng = 0; ng < 4; ++ng) {
                unsigned b0, b1, b2, b3;
                unsigned bAddr = sBb + (((kt << 4) + l15) * 72 + (ng << 4) + lhi) * 2;
                asm volatile("ldmatrix.sync.aligned.m8n8.x4.trans.shared.b16 {%0,%1,%2,%3}, [%4];\n"
                             : "=r"(b0), "=r"(b1), "=r"(b2), "=r"(b3) : "r"(bAddr));
                mma16816(acc[2 * ng],     a0, a1, a2, a3, b0, b1);
                mma16816(acc[2 * ng + 1], a0, a1, a2, a3, b2, b3);
            }
        }
    }
    const int r = rowBase + (wid << 4) + (lane >> 2);
    __half* vp = g_V + (size_t)head * NN * 64 + (size_t)r * 64;
#pragma unroll
    for (int ng = 0; ng < 4; ++ng) {
        int c0 = ng * 16 + qc;
        *(__half2*)(vp + c0)            = __floats2half2_rn(acc[2 * ng][0], acc[2 * ng][1]);
        *(__half2*)(vp + 512 + c0)      = __floats2half2_rn(acc[2 * ng][2], acc[2 * ng][3]);
        *(__half2*)(vp + c0 + 8)        = __floats2half2_rn(acc[2 * ng + 1][0], acc[2 * ng + 1][1]);
        *(__half2*)(vp + 512 + c0 + 8)  = __floats2half2_rn(acc[2 * ng + 1][2], acc[2 * ng + 1][3]);
    }
}

// ---------------- K2: scores + exponential factors (half outputs) ----------------
__global__ void k_scores(const float* __restrict__ avec) {
    const int n = blockIdx.x;
    const int h = threadIdx.x >> 5;
    const int lane = threadIdx.x & 31;
    const __half* vp = g_V + (size_t)h * NN * 64 + (size_t)n * 64;
    float f0 = __half2float(vp[lane]), f1 = __half2float(vp[lane + 32]);
    float ssrc = f0 * avec[lane]      + f1 * avec[lane + 32];
    float sdst = f0 * avec[64 + lane] + f1 * avec[96 + lane];
#pragma unroll
    for (int o = 16; o > 0; o >>= 1) {
        ssrc += __shfl_xor_sync(0xffffffffu, ssrc, o);
        sdst += __shfl_xor_sync(0xffffffffu, sdst, o);
    }
    if (lane == 0) {
        int idx = h * NN + n;
        g_nssh[idx] = __float2half(-ssrc);
        g_gsh[idx]  = __float2half(expf(-0.8f * ssrc));
        g_sDh[idx]  = __float2half(sdst);
        g_EDh[idx]  = __float2half(expf(sdst));
        g_FDh[idx]  = __float2half(expf(0.2f * sdst));
    }
}

// ---------------- K3: fused attention, 4 warps x 2 row-groups ----------------
// SMEM: sV[2][128*72]h 0..36864 | sSDh[2][128] 36864 | sEDh 37376 | sFDh 37888 |
//       sAdj uint4[128*9] 38400..56832
#define SV_BYTES  18432
#define SM_SDH    36864
#define SM_ADJ    38400
#define ATTN_SMEM 56832

__global__ __launch_bounds__(128, 2) void k_attn() {
    extern __shared__ char smem[];
    const unsigned sbase = (unsigned)__cvta_generic_to_shared(smem);
    uint4* sAdjV = (uint4*)(smem + SM_ADJ);

    const int t = threadIdx.x;
    const int ig0 = blockIdx.x * ITILE;
    const int split = blockIdx.y;
    const int jg0 = split * JCHUNK;
    const int hbase = blockIdx.z * HPERG;

    const int lane = t & 31;
    const int wid  = t >> 5;
    const int l15  = lane & 15;
    const int lhi  = (lane >> 4) << 3;
    const int qc   = (lane & 3) << 1;
    const int rA   = (wid << 4) + (lane >> 2);    // tile-local
    const unsigned bz = (lane < 4) ? 0x3C003C00u : 0u;   // ones-column B frag

    // adjacency tile (uint4, pitch 9)
    {
        const uint4* gAdjV = (const uint4*)g_adjbits;
        for (int idx = t; idx < 1024; idx += 128) {
            int r = idx >> 3, q = idx & 7;
            sAdjV[r * 9 + q] = gAdjV[(size_t)(ig0 + r) * 32 + split * 8 + q];
        }
    }

    // initial prefetch (m=0)
    {
        const char* src = (const char*)(g_V + ((size_t)(hbase * NN) + jg0 + t) * 64);
        unsigned d = sbase + t * 144;
#pragma unroll
        for (int i = 0; i < 8; i++) cp16(d + i * 16, src + i * 16);
        if (t < 48) {
            int a = t >> 4, c = t & 15;
            const __half* arr = (a == 0 ? g_sDh : a == 1 ? g_EDh : g_FDh);
            cp16(sbase + SM_SDH + a * 512 + c * 16,
                 (const char*)(arr + hbase * NN + jg0) + c * 16);
        }
        asm volatile("cp.async.commit_group;");
    }

    for (int hh = 0; hh < HPERG; ++hh) {
        const int h = hbase + hh;
        const int rbg = h * NN + ig0;
        const __half2 nssA = __half2half2(g_nssh[rbg + rA]);
        const __half2 nssB = __half2half2(g_nssh[rbg + rA + 8]);
        const __half2 nssC = __half2half2(g_nssh[rbg + rA + 64]);
        const __half2 nssD = __half2half2(g_nssh[rbg + rA + 72]);
        const __half2 gsA  = __half2half2(g_gsh[rbg + rA]);
        const __half2 gsB  = __half2half2(g_gsh[rbg + rA + 8]);
        const __half2 gsC  = __half2half2(g_gsh[rbg + rA + 64]);
        const __half2 gsD  = __half2half2(g_gsh[rbg + rA + 72]);

        float acc0[8][4], acc1[8][4], az0[4], az1[4];
#pragma unroll
        for (int x = 0; x < 8; x++)
#pragma unroll
            for (int y = 0; y < 4; y++) { acc0[x][y] = 0.f; acc1[x][y] = 0.f; }
#pragma unroll
        for (int y = 0; y < 4; y++) { az0[y] = 0.f; az1[y] = 0.f; }

        for (int jt = 0; jt < 8; ++jt) {
            const int m = hh * 8 + jt;
            const int buf = m & 1;
            asm volatile("cp.async.wait_group 0;");
            __syncthreads();

            if (m + 1 < HPERG * 8) {
                const int m2 = m + 1;
                const int h2 = hbase + (m2 >> 3), jt2 = m2 & 7, buf2 = m2 & 1;
                const char* src = (const char*)(g_V + ((size_t)(h2 * NN) + jg0 + jt2 * 128 + t) * 64);
                unsigned d = sbase + buf2 * SV_BYTES + t * 144;
#pragma unroll
                for (int i = 0; i < 8; i++) cp16(d + i * 16, src + i * 16);
                if (t < 48) {
                    int a = t >> 4, c = t & 15;
                    const __half* arr = (a == 0 ? g_sDh : a == 1 ? g_EDh : g_FDh);
                    cp16(sbase + SM_SDH + a * 512 + buf2 * 256 + c * 16,
                         (const char*)(arr + h2 * NN + jg0 + jt2 * 128) + c * 16);
                }
            }
            asm volatile("cp.async.commit_group;");

            const uint4 awA = sAdjV[rA * 9 + jt];
            const uint4 awB = sAdjV[(rA + 8) * 9 + jt];
            const uint4 awC = sAdjV[(rA + 64) * 9 + jt];
            const uint4 awD = sAdjV[(rA + 72) * 9 + jt];
            const char* sdb = smem + SM_SDH + buf * 256;
            const unsigned vbase = sbase + buf * SV_BYTES;

#pragma unroll
            for (int kt = 0; kt < 8; ++kt) {
                const unsigned o = (kt << 5) + (qc << 1);
                const unsigned sdL = *(const unsigned*)(sdb + o);
                const unsigned sdH = *(const unsigned*)(sdb + o + 16);
                const unsigned edL = *(const unsigned*)(sdb + 512 + o);
                const unsigned edH = *(const unsigned*)(sdb + 512 + o + 16);
                const __half2  fdL = *(const __half2*)(sdb + 1024 + o);
                const __half2  fdH = *(const __half2*)(sdb + 1024 + o + 16);

                const int sh = ((kt & 1) << 4) + qc;
                const int wsel4 = kt >> 1;
                const unsigned wA = ((wsel4 == 0) ? awA.x : (wsel4 == 1) ? awA.y : (wsel4 == 2) ? awA.z : awA.w) >> sh;
                const unsigned wB = ((wsel4 == 0) ? awB.x : (wsel4 == 1) ? awB.y : (wsel4 == 2) ? awB.z : awB.w) >> sh;
                const unsigned wC = ((wsel4 == 0) ? awC.x : (wsel4 == 1) ? awC.y : (wsel4 == 2) ? awC.z : awC.w) >> sh;
                const unsigned wD = ((wsel4 == 0) ? awD.x : (wsel4 == 1) ? awD.y : (wsel4 == 2) ? awD.z : awD.w) >> sh;

                const unsigned a0 = wval(sdL, edL, __hmul2(gsA, fdL), nssA, bmask(wA));
                const unsigned a1 = wval(sdL, edL, __hmul2(gsB, fdL), nssB, bmask(wB));
                const unsigned a2 = wval(sdH, edH, __hmul2(gsA, fdH), nssA, bmask(wA >> 8));
                const unsigned a3 = wval(sdH, edH, __hmul2(gsB, fdH), nssB, bmask(wB >> 8));
                const unsigned c0 = wval(sdL, edL, __hmul2(gsC, fdL), nssC, bmask(wC));
                const unsigned c1 = wval(sdL, edL, __hmul2(gsD, fdL), nssD, bmask(wD));
                const unsigned c2 = wval(sdH, edH, __hmul2(gsC, fdH), nssC, bmask(wC >> 8));
                const unsigned c3 = wval(sdH, edH, __hmul2(gsD, fdH), nssD, bmask(wD >> 8));

#pragma unroll
                for (int ng = 0; ng < 4; ++ng) {
                    unsigned b0, b1, b2, b3;
                    unsigned bAddr = vbase + (((kt << 4) + l15) * VPITCH + (ng << 4) + lhi) * 2;
                    asm volatile("ldmatrix.sync.aligned.m8n8.x4.trans.shared.b16 {%0,%1,%2,%3}, [%4];\n"
                                 : "=r"(b0), "=r"(b1), "=r"(b2), "=r"(b3) : "r"(bAddr));
                    mma16816(acc0[2 * ng],     a0, a1, a2, a3, b0, b1);
                    mma16816(acc0[2 * ng + 1], a0, a1, a2, a3, b2, b3);
                    mma16816(acc1[2 * ng],     c0, c1, c2, c3, b0, b1);
                    mma16816(acc1[2 * ng + 1], c0, c1, c2, c3, b2, b3);
                }
                mma16816(az0, a0, a1, a2, a3, bz, bz);
                mma16816(az1, c0, c1, c2, c3, bz, bz);
            }
        } // jt

        if ((lane & 3) == 0) {
            const int zb = split * NN * HEADS;
            g_Z[zb + (ig0 + rA)      * HEADS + h] = az0[0];
            g_Z[zb + (ig0 + rA + 8)  * HEADS + h] = az0[2];
            g_Z[zb + (ig0 + rA + 64) * HEADS + h] = az1[0];
            g_Z[zb + (ig0 + rA + 72) * HEADS + h] = az1[2];
        }
#pragma unroll
        for (int g = 0; g < 2; ++g) {
            float (*ac)[4] = g ? acc1 : acc0;
            float* gaBase = g_acc + ((size_t)split << 21)
                          + (size_t)(ig0 + g * 64 + rA) * 512 + (h << 6) + qc;
#pragma unroll
            for (int nt = 0; nt < 8; ++nt) {
                float* p = gaBase + (nt << 3);
                p[0]    = ac[nt][0];
                p[1]    = ac[nt][1];
                p[4096] = ac[nt][2];
                p[4097] = ac[nt][3];
            }
        }
    } // hh
}

// ---------------- K4: combine splits, normalize, head-mean, LayerNorm ----------------
__global__ void k_finalize(const float* __restrict__ gamma, const float* __restrict__ beta,
                           float* __restrict__ out) {
    const int i = blockIdx.x;
    const int f = threadIdx.x;
    float m = 0.f;
#pragma unroll
    for (int h = 0; h < HEADS; h++) {
        float num = 0.f, z = 0.f;
#pragma unroll
        for (int s = 0; s < NSPLIT; s++) {
            num += g_acc[((size_t)s << 21) + (size_t)i * 512 + h * OUT_F + f];
            z   += g_Z[s * NN * HEADS + i * HEADS + h];
        }
        m += num / z;
    }
    m *= (1.f / HEADS);

    __shared__ float red[64];
    red[f] = m;
    __syncthreads();
#pragma unroll
    for (int o = 32; o > 0; o >>= 1) {
        if (f < o) red[f] += red[f + o];
        __syncthreads();
    }
    float mu = red[0] * (1.f / 64.f);
    __syncthreads();
    float d = m - mu;
    red[f] = d * d;
    __syncthreads();
#pragma unroll
    for (int o = 32; o > 0; o >>= 1) {
        if (f < o) red[f] += red[f + o];
        __syncthreads();
    }
    float var = red[0] * (1.f / 64.f);
    out[i * OUT_F + f] = d * rsqrtf(var + 1e-5f) * gamma[f] + beta[f];
}

// ---------------- launch ----------------
extern "C" void kernel_launch(void* const* d_in, const int* in_sizes, int n_in,
                              void* d_out, int out_size) {
    const float* hmat  = (const float*)d_in[0];
    const int*   adj   = (const int*)  d_in[1];
    const float* W     = (const float*)d_in[2];
    const float* avec  = (const float*)d_in[3];
    const float* gamma = (const float*)d_in[4];
    const float* beta  = (const float*)d_in[5];
    float* out = (float*)d_out;

    k_pack_adj<<<(NN * NN) / 256, 256>>>(adj);
    k_cvt<<<1152, 256>>>(hmat, W);
    k_gemm_ht<<<dim3(8, 32), 256>>>();
    k_scores<<<NN, 256>>>(avec);
    cudaFuncSetAttribute(k_attn, cudaFuncAttributeMaxDynamicSharedMemorySize, ATTN_SMEM);
    k_attn<<<dim3(NN / ITILE, NSPLIT, HGRP), 128, ATTN_SMEM>>>();
    k_finalize<<<NN, 64>>>(gamma, beta, out);
}

// round 5
// speedup vs baseline: 2.3259x; 1.1996x over previous
#include <cuda_runtime.h>
#include <cuda_fp16.h>

#define NN      4096
#define HEADS   8
#define OUT_F   64
#define ITILE   128
#define VPITCH  72     // halfs per sV row (144B)

__device__ __half   g_hh[NN * 256];
__device__ __half   g_Wh[256 * 512];
__device__ __half   g_V[(size_t)HEADS * NN * OUT_F];
__device__ __half   g_gsh [HEADS * NN];
__device__ __half   g_EDh [HEADS * NN];
__device__ __half   g_FDh [HEADS * NN];
__device__ unsigned g_adjbits[NN * (NN / 32)];
__device__ float    g_hp[(size_t)NN * 512];

__device__ __forceinline__ void cp16(unsigned dst, const void* src) {
    asm volatile("cp.async.cg.shared.global [%0], [%1], 16;"
                 :: "r"(dst), "l"(__cvta_generic_to_global(src)));
}
__device__ __forceinline__ __half2 u2h2(unsigned x) { return *reinterpret_cast<__half2*>(&x); }
__device__ __forceinline__ unsigned h22u(__half2 x) { return *reinterpret_cast<unsigned*>(&x); }
// 2 adjacency bits -> half2 keep-mask
__device__ __forceinline__ unsigned bmask(unsigned b) {
    return ((b & 1u) * 0xFFFFu) | ((b & 2u) * 0x7FFF8000u);
}
// w = adj ? max(ed, gs*fd) : 0   (lrelu(x)=max(x,0.2x) => exp factorization)
__device__ __forceinline__ unsigned wval(unsigned ed, __half2 gs, __half2 fd, unsigned am) {
    return h22u(__hmax2(u2h2(ed), __hmul2(gs, fd))) & am;
}
__device__ __forceinline__ void mma16816(float* c, unsigned a0, unsigned a1,
                                         unsigned a2, unsigned a3,
                                         unsigned b0, unsigned b1) {
    asm volatile("mma.sync.aligned.m16n8k16.row.col.f32.f16.f16.f32 "
                 "{%0,%1,%2,%3}, {%4,%5,%6,%7}, {%8,%9}, {%0,%1,%2,%3};\n"
                 : "+f"(c[0]), "+f"(c[1]), "+f"(c[2]), "+f"(c[3])
                 : "r"(a0), "r"(a1), "r"(a2), "r"(a3), "r"(b0), "r"(b1));
}

// ---------------- K0: pack adjacency into bitmask ----------------
__global__ void k_pack_adj(const int* __restrict__ adj) {
    int idx = blockIdx.x * blockDim.x + threadIdx.x;
    int v = adj[idx];
    unsigned m = __ballot_sync(0xffffffffu, v > 0);
    if ((threadIdx.x & 31) == 0) g_adjbits[idx >> 5] = m;
}

// ---------------- K0b: convert h, W to half ----------------
__global__ void k_cvt(const float* __restrict__ hmat, const float* __restrict__ W) {
    int i = blockIdx.x * 256 + threadIdx.x;
    if (i < 262144) {
        float4 v = ((const float4*)hmat)[i];
        ((__half2*)g_hh)[2 * i]     = __floats2half2_rn(v.x, v.y);
        ((__half2*)g_hh)[2 * i + 1] = __floats2half2_rn(v.z, v.w);
    } else {
        int j = i - 262144;
        float4 v = ((const float4*)W)[j];
        ((__half2*)g_Wh)[2 * j]     = __floats2half2_rn(v.x, v.y);
        ((__half2*)g_Wh)[2 * j + 1] = __floats2half2_rn(v.z, v.w);
    }
}

// ---------------- K1: ht = h @ W (fp16 TC) -> g_V, + fused scores ----------------
__global__ __launch_bounds__(256) void k_gemm_ht(const float* __restrict__ avec) {
    __shared__ __align__(16) __half sA[128 * 72];
    __shared__ __align__(16) __half sB[64 * 72];
    const int t = threadIdx.x, lane = t & 31, wid = t >> 5;
    const int head = blockIdx.x, rowBase = blockIdx.y * 128;
    const int l15 = lane & 15, lhi = (lane >> 4) << 3, qc = (lane & 3) << 1;
    const unsigned sAb = (unsigned)__cvta_generic_to_shared(sA);
    const unsigned sBb = (unsigned)__cvta_generic_to_shared(sB);

    float acc[8][4];
#pragma unroll
    for (int x = 0; x < 8; x++)
#pragma unroll
        for (int y = 0; y < 4; y++) acc[x][y] = 0.f;

    for (int k0 = 0; k0 < 256; k0 += 64) {
        __syncthreads();
        {
            const char* src = (const char*)(g_hh + (size_t)(rowBase + (t >> 1)) * 256 + k0 + (t & 1) * 32);
            unsigned d = sAb + ((t >> 1) * 72 + (t & 1) * 32) * 2;
            cp16(d, src); cp16(d + 16, src + 16); cp16(d + 32, src + 32); cp16(d + 48, src + 48);
        }
        if (t < 128) {
            const char* src = (const char*)(g_Wh + (size_t)(k0 + (t >> 1)) * 512 + head * 64 + (t & 1) * 32);
            unsigned d = sBb + ((t >> 1) * 72 + (t & 1) * 32) * 2;
            cp16(d, src); cp16(d + 16, src + 16); cp16(d + 32, src + 32); cp16(d + 48, src + 48);
        }
        asm volatile("cp.async.commit_group;");
        asm volatile("cp.async.wait_group 0;");
        __syncthreads();
#pragma unroll
        for (int kt = 0; kt < 4; ++kt) {
            unsigned a0, a1, a2, a3;
            unsigned aAddr = sAb + (((wid << 4) + l15) * 72 + (kt << 4) + lhi) * 2;
            asm volatile("ldmatrix.sync.aligned.m8n8.x4.shared.b16 {%0,%1,%2,%3}, [%4];\n"
                         : "=r"(a0), "=r"(a1), "=r"(a2), "=r"(a3) : "r"(aAddr));
#pragma unroll
            for (int ng = 0; ng < 4; ++ng) {
                unsigned b0, b1, b2, b3;
                unsigned bAddr = sBb + (((kt << 4) + l15) * 72 + (ng << 4) + lhi) * 2;
                asm volatile("ldmatrix.sync.aligned.m8n8.x4.trans.shared.b16 {%0,%1,%2,%3}, [%4];\n"
                             : "=r"(b0), "=r"(b1), "=r"(b2), "=r"(b3) : "r"(bAddr));
                mma16816(acc[2 * ng],     a0, a1, a2, a3, b0, b1);
                mma16816(acc[2 * ng + 1], a0, a1, a2, a3, b2, b3);
            }
        }
    }
    const int r = rowBase + (wid << 4) + (lane >> 2);
    __half* vp = g_V + (size_t)head * NN * 64 + (size_t)r * 64;
#pragma unroll
    for (int ng = 0; ng < 4; ++ng) {
        int c0 = ng * 16 + qc;
        *(__half2*)(vp + c0)            = __floats2half2_rn(acc[2 * ng][0], acc[2 * ng][1]);
        *(__half2*)(vp + 512 + c0)      = __floats2half2_rn(acc[2 * ng][2], acc[2 * ng][3]);
        *(__half2*)(vp + c0 + 8)        = __floats2half2_rn(acc[2 * ng + 1][0], acc[2 * ng + 1][1]);
        *(__half2*)(vp + 512 + c0 + 8)  = __floats2half2_rn(acc[2 * ng + 1][2], acc[2 * ng + 1][3]);
    }

    // fused scores: ssrc/sdst for rows r and r+8
    float s0 = 0.f, d0 = 0.f, s1 = 0.f, d1 = 0.f;
#pragma unroll
    for (int ng = 0; ng < 4; ++ng) {
        int c0 = ng * 16 + qc;
        float as0 = avec[c0],      as1 = avec[c0 + 1];
        float as8 = avec[c0 + 8],  as9 = avec[c0 + 9];
        float ad0 = avec[64 + c0], ad1 = avec[64 + c0 + 1];
        float ad8 = avec[64 + c0 + 8], ad9 = avec[64 + c0 + 9];
        s0 += acc[2*ng][0]*as0 + acc[2*ng][1]*as1 + acc[2*ng+1][0]*as8 + acc[2*ng+1][1]*as9;
        d0 += acc[2*ng][0]*ad0 + acc[2*ng][1]*ad1 + acc[2*ng+1][0]*ad8 + acc[2*ng+1][1]*ad9;
        s1 += acc[2*ng][2]*as0 + acc[2*ng][3]*as1 + acc[2*ng+1][2]*as8 + acc[2*ng+1][3]*as9;
        d1 += acc[2*ng][2]*ad0 + acc[2*ng][3]*ad1 + acc[2*ng+1][2]*ad8 + acc[2*ng+1][3]*ad9;
    }
#pragma unroll
    for (int o = 1; o < 4; o <<= 1) {
        s0 += __shfl_xor_sync(0xffffffffu, s0, o);
        d0 += __shfl_xor_sync(0xffffffffu, d0, o);
        s1 += __shfl_xor_sync(0xffffffffu, s1, o);
        d1 += __shfl_xor_sync(0xffffffffu, d1, o);
    }
    if ((lane & 3) == 0) {
        int idx = head * NN + r;
        g_gsh[idx]     = __float2half(expf(-0.8f * s0));
        g_EDh[idx]     = __float2half(expf(d0));
        g_FDh[idx]     = __float2half(expf(0.2f * d0));
        g_gsh[idx + 8] = __float2half(expf(-0.8f * s1));
        g_EDh[idx + 8] = __float2half(expf(d1));
        g_FDh[idx + 8] = __float2half(expf(0.2f * d1));
    }
}

// ---------------- K3: fused attention, one CTA per (itile, head), full j ----------------
// SMEM: sV[2][128*72]h 0..36864 | sED[2][128]h 36864..37888 (a*512+buf*256)
//       | sFD interleaved in same block | sAdj[2][128]uint4 37888..41984
#define SV_BYTES  18432
#define SM_ED     36864
#define SM_ADJ    37888
#define ATTN_SMEM 41984

__global__ __launch_bounds__(128, 2) void k_attn() {
    extern __shared__ char smem[];
    const unsigned sbase = (unsigned)__cvta_generic_to_shared(smem);

    const int t = threadIdx.x;
    const int ig0 = blockIdx.x * ITILE;
    const int h = blockIdx.y;

    const int lane = t & 31;
    const int wid  = t >> 5;
    const int l15  = lane & 15;
    const int lhi  = (lane >> 4) << 3;
    const int qc   = (lane & 3) << 1;
    const int rA   = (wid << 4) + (lane >> 2);    // tile-local row
    const unsigned bz = (lane < 4) ? 0x3C003C00u : 0u;   // ones-column B frag

    const int rbg = h * NN + ig0;
    const __half2 gsA = __half2half2(g_gsh[rbg + rA]);
    const __half2 gsB = __half2half2(g_gsh[rbg + rA + 8]);
    const __half2 gsC = __half2half2(g_gsh[rbg + rA + 64]);
    const __half2 gsD = __half2half2(g_gsh[rbg + rA + 72]);

    // prefetch tile jt2 into buffer buf2
    auto prefetch = [&](int jt2, int buf2) {
        const char* src = (const char*)(g_V + ((size_t)(h * NN) + jt2 * 128 + t) * 64);
        unsigned d = sbase + buf2 * SV_BYTES + t * 144;
#pragma unroll
        for (int i = 0; i < 8; i++) cp16(d + i * 16, src + i * 16);
        cp16(sbase + SM_ADJ + buf2 * 2048 + t * 16,
             (const char*)(g_adjbits + (size_t)(ig0 + t) * 128 + jt2 * 4));
        if (t < 32) {
            int a = t >> 4, c = t & 15;
            const __half* arr = a ? g_FDh : g_EDh;
            cp16(sbase + SM_ED + a * 512 + buf2 * 256 + c * 16,
                 (const char*)(arr + h * NN + jt2 * 128) + c * 16);
        }
        asm volatile("cp.async.commit_group;");
    };

    prefetch(0, 0);

    float acc0[8][4], acc1[8][4], az0[4], az1[4];
#pragma unroll
    for (int x = 0; x < 8; x++)
#pragma unroll
        for (int y = 0; y < 4; y++) { acc0[x][y] = 0.f; acc1[x][y] = 0.f; }
#pragma unroll
    for (int y = 0; y < 4; y++) { az0[y] = 0.f; az1[y] = 0.f; }

    for (int jt = 0; jt < 32; ++jt) {
        const int buf = jt & 1;
        asm volatile("cp.async.wait_group 0;");
        __syncthreads();
        if (jt + 1 < 32) prefetch(jt + 1, buf ^ 1);
        else asm volatile("cp.async.commit_group;");

        const uint4* sAdjB = (const uint4*)(smem + SM_ADJ + buf * 2048);
        const uint4 awA = sAdjB[rA];
        const uint4 awB = sAdjB[rA + 8];
        const uint4 awC = sAdjB[rA + 64];
        const uint4 awD = sAdjB[rA + 72];
        const char* edb = smem + SM_ED + buf * 256;
        const char* fdb = smem + SM_ED + 512 + buf * 256;
        const unsigned vbase = sbase + buf * SV_BYTES;

#pragma unroll
        for (int kt = 0; kt < 8; ++kt) {
            const unsigned o = (kt << 5) + (qc << 1);
            const unsigned edL = *(const unsigned*)(edb + o);
            const unsigned edH = *(const unsigned*)(edb + o + 16);
            const __half2  fdL = *(const __half2*)(fdb + o);
            const __half2  fdH = *(const __half2*)(fdb + o + 16);

            const int sh = ((kt & 1) << 4) + qc;
            const int w4 = kt >> 1;
            const unsigned wA = ((w4 == 0) ? awA.x : (w4 == 1) ? awA.y : (w4 == 2) ? awA.z : awA.w) >> sh;
            const unsigned wB = ((w4 == 0) ? awB.x : (w4 == 1) ? awB.y : (w4 == 2) ? awB.z : awB.w) >> sh;
            const unsigned wC = ((w4 == 0) ? awC.x : (w4 == 1) ? awC.y : (w4 == 2) ? awC.z : awC.w) >> sh;
            const unsigned wD = ((w4 == 0) ? awD.x : (w4 == 1) ? awD.y : (w4 == 2) ? awD.z : awD.w) >> sh;

            const unsigned a0 = wval(edL, gsA, fdL, bmask(wA));
            const unsigned a1 = wval(edL, gsB, fdL, bmask(wB));
            const unsigned a2 = wval(edH, gsA, fdH, bmask(wA >> 8));
            const unsigned a3 = wval(edH, gsB, fdH, bmask(wB >> 8));
            const unsigned c0 = wval(edL, gsC, fdL, bmask(wC));
            const unsigned c1 = wval(edL, gsD, fdL, bmask(wD));
            const unsigned c2 = wval(edH, gsC, fdH, bmask(wC >> 8));
            const unsigned c3 = wval(edH, gsD, fdH, bmask(wD >> 8));

#pragma unroll
            for (int ng = 0; ng < 4; ++ng) {
                unsigned b0, b1, b2, b3;
                unsigned bAddr = vbase + (((kt << 4) + l15) * VPITCH + (ng << 4) + lhi) * 2;
                asm volatile("ldmatrix.sync.aligned.m8n8.x4.trans.shared.b16 {%0,%1,%2,%3}, [%4];\n"
                             : "=r"(b0), "=r"(b1), "=r"(b2), "=r"(b3) : "r"(bAddr));
                mma16816(acc0[2 * ng],     a0, a1, a2, a3, b0, b1);
                mma16816(acc0[2 * ng + 1], a0, a1, a2, a3, b2, b3);
                mma16816(acc1[2 * ng],     c0, c1, c2, c3, b0, b1);
                mma16816(acc1[2 * ng + 1], c0, c1, c2, c3, b2, b3);
            }
            mma16816(az0, a0, a1, a2, a3, bz, bz);
            mma16816(az1, c0, c1, c2, c3, bz, bz);
        }
    } // jt

    // Z broadcast within each 4-lane group (col 0 lives at lane&3==0)
    const float iA = 1.f / __shfl_sync(0xffffffffu, az0[0], lane & 28);
    const float iB = 1.f / __shfl_sync(0xffffffffu, az0[2], lane & 28);
    const float iC = 1.f / __shfl_sync(0xffffffffu, az1[0], lane & 28);
    const float iD = 1.f / __shfl_sync(0xffffffffu, az1[2], lane & 28);

    float* p0 = g_hp + (size_t)(ig0 + rA) * 512 + (h << 6);
    float* p2 = g_hp + (size_t)(ig0 + rA + 64) * 512 + (h << 6);
#pragma unroll
    for (int ng = 0; ng < 4; ++ng) {
        const int c0 = ng * 16 + qc;
        *(float2*)(p0 + c0)            = make_float2(acc0[2*ng][0] * iA, acc0[2*ng][1] * iA);
        *(float2*)(p0 + c0 + 8)        = make_float2(acc0[2*ng+1][0] * iA, acc0[2*ng+1][1] * iA);
        *(float2*)(p0 + 4096 + c0)     = make_float2(acc0[2*ng][2] * iB, acc0[2*ng][3] * iB);
        *(float2*)(p0 + 4096 + c0 + 8) = make_float2(acc0[2*ng+1][2] * iB, acc0[2*ng+1][3] * iB);
        *(float2*)(p2 + c0)            = make_float2(acc1[2*ng][0] * iC, acc1[2*ng][1] * iC);
        *(float2*)(p2 + c0 + 8)        = make_float2(acc1[2*ng+1][0] * iC, acc1[2*ng+1][1] * iC);
        *(float2*)(p2 + 4096 + c0)     = make_float2(acc1[2*ng][2] * iD, acc1[2*ng][3] * iD);
        *(float2*)(p2 + 4096 + c0 + 8) = make_float2(acc1[2*ng+1][2] * iD, acc1[2*ng+1][3] * iD);
    }
}

// ---------------- K4: head-mean + LayerNorm ----------------
__global__ void k_finalize(const float* __restrict__ gamma, const float* __restrict__ beta,
                           float* __restrict__ out) {
    const int i = blockIdx.x;
    const int f = threadIdx.x;
    const float* hp = g_hp + (size_t)i * 512;
    float m = 0.f;
#pragma unroll
    for (int h = 0; h < HEADS; h++) m += hp[h * 64 + f];
    m *= (1.f / HEADS);

    __shared__ float red[64];
    red[f] = m;
    __syncthreads();
#pragma unroll
    for (int o = 32; o > 0; o >>= 1) {
        if (f < o) red[f] += red[f + o];
        __syncthreads();
    }
    float mu = red[0] * (1.f / 64.f);
    __syncthreads();
    float d = m - mu;
    red[f] = d * d;
    __syncthreads();
#pragma unroll
    for (int o = 32; o > 0; o >>= 1) {
        if (f < o) red[f] += red[f + o];
        __syncthreads();
    }
    float var = red[0] * (1.f / 64.f);
    out[i * OUT_F + f] = d * rsqrtf(var + 1e-5f) * gamma[f] + beta[f];
}

// ---------------- launch ----------------
extern "C" void kernel_launch(void* const* d_in, const int* in_sizes, int n_in,
                              void* d_out, int out_size) {
    const float* hmat  = (const float*)d_in[0];
    const int*   adj   = (const int*)  d_in[1];
    const float* W     = (const float*)d_in[2];
    const float* avec  = (const float*)d_in[3];
    const float* gamma = (const float*)d_in[4];
    const float* beta  = (const float*)d_in[5];
    float* out = (float*)d_out;

    k_pack_adj<<<(NN * NN) / 256, 256>>>(adj);
    k_cvt<<<1152, 256>>>(hmat, W);
    k_gemm_ht<<<dim3(8, 32), 256>>>(avec);
    k_attn<<<dim3(NN / ITILE, HEADS), 128, ATTN_SMEM>>>();
    k_finalize<<<NN, 64>>>(gamma, beta, out);
}